// round 5
// baseline (speedup 1.0000x reference)
#include <cuda_runtime.h>

// Voxel-grid mean sampling — exact replication of the reference construction:
//   batch = searchsorted(offset, i, right)
//   start = per-batch min(coord)
//   grid  = floor((coord - start[batch]) * 20.0f)   // XLA rewrites /0.05f to *RN(1/0.05f)=*20.0f
//   G     = max(grid)+1  (computed on device)
//   key   = ((b*G+gx)*G+gy)*G+gz  (dense table of B*G^3 counts)
//   voxels enumerated in ascending key order (== jnp.unique sort order)
// Outputs (float32, flattened into d_out):
//   [0,3N) n_p voxel means (zero-padded), [3N,3N+B) n_o cumulative voxel
//   counts per batch, [3N+B,4N+B) counts per voxel (zero-padded).

#define CHUNK     4096
#define MAXKEYS   (1 << 26)
#define MAXCHUNKS (MAXKEYS / CHUNK)
#define MAXLAUNCH 8192
#define MAXN      (1 << 23)
#define MAXB      1024
#define INV_VOXEL 20.0f   // RN(1/0.05f) == 20.0f exactly

__device__ unsigned d_voxCount[MAXKEYS];   // histogram, then rank per key
__device__ int      d_pgrid[MAXN];         // packed (b<<21)|(gx<<14)|(gy<<7)|gz
__device__ unsigned d_chunkOcc[MAXCHUNKS];
__device__ unsigned d_chunkPrefix[MAXCHUNKS];
__device__ unsigned d_minMapped[MAXB * 3];
__device__ float    d_start[MAXB * 3];
__device__ int      d_gmax;
__device__ int      d_G, d_G3, d_keySpace, d_nChunks, d_keySpacePad;

__device__ __forceinline__ unsigned fmap(float f) {
    unsigned u = __float_as_uint(f);
    return (u & 0x80000000u) ? ~u : (u | 0x80000000u);
}
__device__ __forceinline__ float funmap(unsigned m) {
    unsigned u = (m & 0x80000000u) ? (m & 0x7FFFFFFFu) : ~m;
    return __uint_as_float(u);
}

// first b with offset[b] > i (searchsorted right)
__device__ __forceinline__ int batchOf(int i, const int* __restrict__ off, int B) {
    int lo = 0, hi = B;
    while (lo < hi) {
        int mid = (lo + hi) >> 1;
        if (__ldg(off + mid) <= i) lo = mid + 1; else hi = mid;
    }
    return lo;
}

__global__ void kInitMin(int n) {
    int i = blockIdx.x * blockDim.x + threadIdx.x;
    if (i < n) d_minMapped[i] = 0xFFFFFFFFu;
    if (i == 0) d_gmax = 0;
}

__global__ void kMin(const float* __restrict__ coord, const int* __restrict__ off,
                     int N, int B) {
    int i = blockIdx.x * blockDim.x + threadIdx.x;
    int j = min(i, N - 1);                       // clamp: min is idempotent
    int b = batchOf(j, off, B);
    float x = __ldg(coord + 3 * j + 0);
    float y = __ldg(coord + 3 * j + 1);
    float z = __ldg(coord + 3 * j + 2);
    const unsigned full = 0xFFFFFFFFu;
    int b0 = __shfl_sync(full, b, 0);
    if (__all_sync(full, b == b0)) {
        #pragma unroll
        for (int o = 16; o > 0; o >>= 1) {
            x = fminf(x, __shfl_down_sync(full, x, o));
            y = fminf(y, __shfl_down_sync(full, y, o));
            z = fminf(z, __shfl_down_sync(full, z, o));
        }
        if ((threadIdx.x & 31) == 0) {
            atomicMin(&d_minMapped[3 * b + 0], fmap(x));
            atomicMin(&d_minMapped[3 * b + 1], fmap(y));
            atomicMin(&d_minMapped[3 * b + 2], fmap(z));
        }
    } else {
        atomicMin(&d_minMapped[3 * b + 0], fmap(x));
        atomicMin(&d_minMapped[3 * b + 1], fmap(y));
        atomicMin(&d_minMapped[3 * b + 2], fmap(z));
    }
}

__global__ void kUnmap(int n) {
    int i = blockIdx.x * blockDim.x + threadIdx.x;
    if (i < n) d_start[i] = funmap(d_minMapped[i]);
}

// grid computation: ONCE, packed; also reduce global max grid index
__global__ void kGrid(const float* __restrict__ coord, const int* __restrict__ off,
                      int N, int B) {
    int i = blockIdx.x * blockDim.x + threadIdx.x;
    int j = min(i, N - 1);
    int b = batchOf(j, off, B);
    float sx = __ldg(d_start + 3 * b + 0);
    float sy = __ldg(d_start + 3 * b + 1);
    float sz = __ldg(d_start + 3 * b + 2);
    float x = __ldg(coord + 3 * j + 0);
    float y = __ldg(coord + 3 * j + 1);
    float z = __ldg(coord + 3 * j + 2);
    int gx = (int)floorf((x - sx) * INV_VOXEL);
    int gy = (int)floorf((y - sy) * INV_VOXEL);
    int gz = (int)floorf((z - sz) * INV_VOXEL);
    gx = min(max(gx, 0), 127);
    gy = min(max(gy, 0), 127);
    gz = min(max(gz, 0), 127);
    if (i < N)
        d_pgrid[j] = (b << 21) | (gx << 14) | (gy << 7) | gz;
    int m = max(gx, max(gy, gz));
    #pragma unroll
    for (int o = 16; o > 0; o >>= 1)
        m = max(m, __shfl_down_sync(0xFFFFFFFFu, m, o));
    if ((threadIdx.x & 31) == 0) atomicMax(&d_gmax, m);
}

__global__ void kSetup(int B) {
    int G = d_gmax + 1;
    int G3 = G * G * G;
    long long ksl = (long long)B * G3;
    int ks = (ksl > MAXKEYS) ? MAXKEYS : (int)ksl;
    int nc = (ks + CHUNK - 1) / CHUNK;
    d_G = G; d_G3 = G3; d_keySpace = ks;
    d_nChunks = nc; d_keySpacePad = nc * CHUNK;
}

__global__ void kZeroVox() {
    int idx = blockIdx.x * blockDim.x + threadIdx.x;
    int stride = gridDim.x * blockDim.x;
    int n4 = d_keySpacePad >> 2;                 // pad is a multiple of 4096
    uint4 z = make_uint4(0u, 0u, 0u, 0u);
    uint4* p = reinterpret_cast<uint4*>(d_voxCount);
    for (int k = idx; k < n4; k += stride) p[k] = z;
}

__global__ void kZeroOut(float* __restrict__ out, int n) {
    int idx = blockIdx.x * blockDim.x + threadIdx.x;
    int stride = gridDim.x * blockDim.x;
    int n4 = n >> 2;
    uint4 z = make_uint4(0u, 0u, 0u, 0u);
    uint4* p4 = reinterpret_cast<uint4*>(out);
    for (int k = idx; k < n4; k += stride) p4[k] = z;
    for (int k = (n4 << 2) + idx; k < n; k += stride) out[k] = 0.0f;
}

__device__ __forceinline__ int keyOf(int p, int G) {
    int b  = p >> 21;
    int gx = (p >> 14) & 127;
    int gy = (p >> 7) & 127;
    int gz = p & 127;
    return ((b * G + gx) * G + gy) * G + gz;
}

__global__ void kHist(int N) {
    int i = blockIdx.x * blockDim.x + threadIdx.x;
    if (i >= N) return;
    int key = keyOf(d_pgrid[i], d_G);
    atomicAdd(&d_voxCount[key], 1u);
}

__global__ void __launch_bounds__(256) kChunkOcc() {
    __shared__ unsigned wsum[8];
    int nChunks = d_nChunks;
    for (int chunk = blockIdx.x; chunk < nChunks; chunk += gridDim.x) {
        const uint4* p = reinterpret_cast<const uint4*>(d_voxCount + chunk * CHUNK)
                         + threadIdx.x * 4;
        unsigned c = 0;
        #pragma unroll
        for (int k = 0; k < 4; k++) {
            uint4 v = p[k];
            c += (v.x != 0u) + (v.y != 0u) + (v.z != 0u) + (v.w != 0u);
        }
        c = __reduce_add_sync(0xFFFFFFFFu, c);
        if ((threadIdx.x & 31) == 0) wsum[threadIdx.x >> 5] = c;
        __syncthreads();
        if (threadIdx.x == 0) {
            unsigned s = 0;
            #pragma unroll
            for (int w = 0; w < 8; w++) s += wsum[w];
            d_chunkOcc[chunk] = s;
        }
        __syncthreads();
    }
}

__global__ void kScan() {
    __shared__ unsigned s[1024];
    __shared__ unsigned carry;
    int nChunks = d_nChunks;
    int t = threadIdx.x;
    if (t == 0) carry = 0;
    __syncthreads();
    for (int base = 0; base < nChunks; base += 1024) {
        unsigned v = (base + t < nChunks) ? d_chunkOcc[base + t] : 0u;
        s[t] = v;
        __syncthreads();
        for (int o = 1; o < 1024; o <<= 1) {
            unsigned a = (t >= o) ? s[t - o] : 0u;
            __syncthreads();
            s[t] += a;
            __syncthreads();
        }
        if (base + t < nChunks) d_chunkPrefix[base + t] = carry + s[t] - v;
        __syncthreads();
        if (t == 0) carry += s[1023];
        __syncthreads();
    }
}

__global__ void __launch_bounds__(256) kRank(float* __restrict__ out, int N, int B) {
    float* out_no = out + 3 * N;
    float* out_counts = out + 3 * N + B;
    __shared__ unsigned warpS[8];
    __shared__ unsigned wexcl[8];
    int nChunks = d_nChunks;
    int G3 = d_G3;
    for (int chunk = blockIdx.x; chunk < nChunks; chunk += gridDim.x) {
        int keyBase = chunk * CHUNK;
        unsigned cnts[16];
        const uint4* p = reinterpret_cast<const uint4*>(d_voxCount + keyBase)
                         + threadIdx.x * 4;
        unsigned tot = 0;
        #pragma unroll
        for (int k = 0; k < 4; k++) {
            uint4 v = p[k];
            cnts[4 * k + 0] = v.x; cnts[4 * k + 1] = v.y;
            cnts[4 * k + 2] = v.z; cnts[4 * k + 3] = v.w;
            tot += (v.x != 0u) + (v.y != 0u) + (v.z != 0u) + (v.w != 0u);
        }
        unsigned lane = threadIdx.x & 31, wid = threadIdx.x >> 5;
        unsigned incl = tot;
        #pragma unroll
        for (int o = 1; o < 32; o <<= 1) {
            unsigned a = __shfl_up_sync(0xFFFFFFFFu, incl, o);
            if (lane >= o) incl += a;
        }
        if (lane == 31) warpS[wid] = incl;
        __syncthreads();
        if (threadIdx.x == 0) {
            unsigned run = 0;
            #pragma unroll
            for (int w = 0; w < 8; w++) { unsigned v = warpS[w]; wexcl[w] = run; run += v; }
        }
        __syncthreads();
        unsigned rank = d_chunkPrefix[chunk] + wexcl[wid] + (incl - tot);
        int key = keyBase + threadIdx.x * 16;
        #pragma unroll
        for (int k = 0; k < 16; k++, key++) {
            unsigned c = cnts[k];
            unsigned occ = (c != 0u) ? 1u : 0u;
            if (occ) {
                d_voxCount[key] = rank;              // overwrite count with rank
                out_counts[rank] = (float)c;
            }
            if ((key + 1) % G3 == 0) {               // last key of a batch
                int bb = (key + 1) / G3 - 1;
                if (bb < B) out_no[bb] = (float)(rank + occ);  // inclusive cumsum
            }
            rank += occ;
        }
        __syncthreads();
    }
}

__global__ void kScatter(const float* __restrict__ coord, float* __restrict__ out,
                         int N) {
    int i = blockIdx.x * blockDim.x + threadIdx.x;
    if (i >= N) return;
    int key = keyOf(d_pgrid[i], d_G);
    unsigned r = d_voxCount[key];
    atomicAdd(&out[3 * r + 0], __ldg(coord + 3 * i + 0));
    atomicAdd(&out[3 * r + 1], __ldg(coord + 3 * i + 1));
    atomicAdd(&out[3 * r + 2], __ldg(coord + 3 * i + 2));
}

__global__ void kFinalize(float* __restrict__ out, int N, int B) {
    int r = blockIdx.x * blockDim.x + threadIdx.x;
    if (r >= N) return;
    float c = out[3 * N + B + r];
    if (c > 0.5f) {
        out[3 * r + 0] = __fdiv_rn(out[3 * r + 0], c);
        out[3 * r + 1] = __fdiv_rn(out[3 * r + 1], c);
        out[3 * r + 2] = __fdiv_rn(out[3 * r + 2], c);
    }
}

extern "C" void kernel_launch(void* const* d_in, const int* in_sizes, int n_in,
                              void* d_out, int out_size) {
    const float* coord  = (const float*)d_in[0];
    const int*   offset = (const int*)d_in[1];
    int N = in_sizes[0] / 3;
    int B = in_sizes[1];
    float* out = (float*)d_out;

    int nb = (N + 255) / 256;

    kInitMin<<<(B * 3 + 255) / 256, 256>>>(B * 3);
    kMin<<<nb, 256>>>(coord, offset, N, B);
    kUnmap<<<(B * 3 + 255) / 256, 256>>>(B * 3);
    kGrid<<<nb, 256>>>(coord, offset, N, B);
    kSetup<<<1, 1>>>(B);
    kZeroVox<<<2048, 256>>>();
    kZeroOut<<<2048, 256>>>(out, out_size);
    kHist<<<nb, 256>>>(N);
    kChunkOcc<<<MAXLAUNCH, 256>>>();
    kScan<<<1, 1024>>>();
    kRank<<<MAXLAUNCH, 256>>>(out, N, B);
    kScatter<<<nb, 256>>>(coord, out, N);
    kFinalize<<<nb, 256>>>(out, N, B);
}

// round 6
// speedup vs baseline: 2.2661x; 2.2661x over previous
#include <cuda_runtime.h>

// Voxel-grid mean sampling (reference-exact construction):
//   batch = searchsorted(offset, i, right); start = per-batch min(coord)
//   grid  = floor((coord - start[batch]) * 20.0f)   // == XLA's /0.05 rewrite
//   G     = max(grid)+1 ; key = ((b*G+gx)*G+gy)*G+gz ; voxels in ascending key order
// Outputs (float32): [0,3N) n_p means, [3N,3N+B) n_o cumsum voxels/batch,
// [3N+B,4N+B) counts (zero-padded).

#define CHUNK     4096
#define MAXKEYS   (1 << 26)
#define MAXCHUNKS (MAXKEYS / CHUNK)
#define MAXN      (1 << 23)
#define MAXB      256
#define INV_VOXEL 20.0f        // RN(1/0.05f) == 20.0f exactly
#define ST_AGG    (1u << 30)
#define ST_INC    (2u << 30)
#define VALMASK   ((1u << 30) - 1u)

__device__ unsigned d_voxCount[MAXKEYS];   // histogram, then rank per key
__device__ int      d_ckey[MAXN];          // per-point dense key
__device__ unsigned d_tileStatus[MAXCHUNKS];
__device__ unsigned d_minMapped[MAXB * 3];
__device__ unsigned d_maxMapped[MAXB * 3];
__device__ float    d_start[MAXB * 3];
__device__ int      d_G, d_G3, d_keySpacePad, d_nChunks;
__device__ unsigned d_ticket;

__device__ __forceinline__ unsigned fmap(float f) {
    unsigned u = __float_as_uint(f);
    return (u & 0x80000000u) ? ~u : (u | 0x80000000u);
}
__device__ __forceinline__ float funmap(unsigned m) {
    unsigned u = (m & 0x80000000u) ? (m & 0x7FFFFFFFu) : ~m;
    return __uint_as_float(u);
}
// first b with offset[b] > i (searchsorted right)
__device__ __forceinline__ int batchOf(int i, const int* __restrict__ off, int B) {
    int lo = 0, hi = B;
    while (lo < hi) {
        int mid = (lo + hi) >> 1;
        if (__ldg(off + mid) <= i) lo = mid + 1; else hi = mid;
    }
    return lo;
}

__global__ void kInit(int n) {
    int i = blockIdx.x * blockDim.x + threadIdx.x;
    if (i < n) { d_minMapped[i] = 0xFFFFFFFFu; d_maxMapped[i] = 0u; }
}

// per-batch min AND max, 8 points/thread, float4 loads
__global__ void kMinMax(const float* __restrict__ coord, const int* __restrict__ off,
                        int N, int B) {
    const unsigned full = 0xFFFFFFFFu;
    int t = blockIdx.x * blockDim.x + threadIdx.x;
    long long base = (long long)t * 8;
    if (base >= N) return;
    int i0 = (int)base;
    int cnt = min(8, N - i0);
    int bf = batchOf(i0, off, B);
    int bl = batchOf(i0 + cnt - 1, off, B);
    if (bf != bl) {   // rare: spans a batch boundary -> per-point atomics
        for (int i = i0; i < i0 + cnt; i++) {
            int b = batchOf(i, off, B);
            float x = __ldg(coord + 3 * i + 0);
            float y = __ldg(coord + 3 * i + 1);
            float z = __ldg(coord + 3 * i + 2);
            atomicMin(&d_minMapped[3 * b + 0], fmap(x));
            atomicMin(&d_minMapped[3 * b + 1], fmap(y));
            atomicMin(&d_minMapped[3 * b + 2], fmap(z));
            atomicMax(&d_maxMapped[3 * b + 0], fmap(x));
            atomicMax(&d_maxMapped[3 * b + 1], fmap(y));
            atomicMax(&d_maxMapped[3 * b + 2], fmap(z));
        }
        return;
    }
    float mn[3] = { 3.4e38f, 3.4e38f, 3.4e38f };
    float mx[3] = { -3.4e38f, -3.4e38f, -3.4e38f };
    if (cnt == 8) {
        const float4* p = reinterpret_cast<const float4*>(coord + (size_t)i0 * 3);
        #pragma unroll
        for (int k = 0; k < 6; k++) {
            float4 v = __ldg(p + k);
            float a[4] = { v.x, v.y, v.z, v.w };
            #pragma unroll
            for (int j = 0; j < 4; j++) {
                int ax = (4 * k + j) % 3;   // compile-time
                mn[ax] = fminf(mn[ax], a[j]);
                mx[ax] = fmaxf(mx[ax], a[j]);
            }
        }
    } else {
        for (int i = i0; i < i0 + cnt; i++) {
            #pragma unroll
            for (int ax = 0; ax < 3; ax++) {
                float v = __ldg(coord + 3 * i + ax);
                mn[ax] = fminf(mn[ax], v);
                mx[ax] = fmaxf(mx[ax], v);
            }
        }
    }
    unsigned act = __activemask();
    if (act == full) {
        int b0 = __shfl_sync(full, bf, 0);
        if (__all_sync(full, bf == b0)) {
            #pragma unroll
            for (int o = 16; o > 0; o >>= 1) {
                #pragma unroll
                for (int ax = 0; ax < 3; ax++) {
                    mn[ax] = fminf(mn[ax], __shfl_down_sync(full, mn[ax], o));
                    mx[ax] = fmaxf(mx[ax], __shfl_down_sync(full, mx[ax], o));
                }
            }
            if ((threadIdx.x & 31) == 0) {
                #pragma unroll
                for (int ax = 0; ax < 3; ax++) {
                    atomicMin(&d_minMapped[3 * bf + ax], fmap(mn[ax]));
                    atomicMax(&d_maxMapped[3 * bf + ax], fmap(mx[ax]));
                }
            }
            return;
        }
    }
    #pragma unroll
    for (int ax = 0; ax < 3; ax++) {
        atomicMin(&d_minMapped[3 * bf + ax], fmap(mn[ax]));
        atomicMax(&d_maxMapped[3 * bf + ax], fmap(mx[ax]));
    }
}

// start[], G, G3, chunk geometry, ticket reset
__global__ void kSetup(int B) {
    __shared__ int sm[256];
    int m = 0;
    for (int b = threadIdx.x; b < B; b += 256) {
        #pragma unroll
        for (int ax = 0; ax < 3; ax++) {
            float s = funmap(d_minMapped[3 * b + ax]);
            float M = funmap(d_maxMapped[3 * b + ax]);
            d_start[3 * b + ax] = s;
            int e = (int)floorf((M - s) * INV_VOXEL);  // == max per-point grid idx
            m = max(m, e);
        }
    }
    sm[threadIdx.x] = m; __syncthreads();
    for (int o = 128; o > 0; o >>= 1) {
        if (threadIdx.x < o) sm[threadIdx.x] = max(sm[threadIdx.x], sm[threadIdx.x + o]);
        __syncthreads();
    }
    if (threadIdx.x == 0) {
        int G = sm[0] + 1;
        long long ks = (long long)B * G * G * G;
        if (ks > MAXKEYS) ks = MAXKEYS;
        int nc = (int)((ks + CHUNK - 1) / CHUNK);
        d_G = G; d_G3 = G * G * G;
        d_nChunks = nc; d_keySpacePad = nc * CHUNK;
        d_ticket = 0u;
    }
}

__global__ void kZeroAll(float* __restrict__ out, int outN) {
    int idx = blockIdx.x * blockDim.x + threadIdx.x;
    int stride = gridDim.x * blockDim.x;
    uint4 z = make_uint4(0u, 0u, 0u, 0u);
    int n4 = d_keySpacePad >> 2;            // pad multiple of 4096
    uint4* p = reinterpret_cast<uint4*>(d_voxCount);
    for (int k = idx; k < n4; k += stride) p[k] = z;
    int nc = d_nChunks;
    for (int k = idx; k < nc; k += stride) d_tileStatus[k] = 0u;
    int o4 = outN >> 2;
    uint4* q = reinterpret_cast<uint4*>(out);
    for (int k = idx; k < o4; k += stride) q[k] = z;
    for (int k = (o4 << 2) + idx; k < outN; k += stride) out[k] = 0.0f;
}

__device__ __forceinline__ int gridKey(float c, float s, int G) {
    int g = (int)floorf((c - s) * INV_VOXEL);
    return min(max(g, 0), G - 1);
}

// fused grid + key store + histogram, 4 points/thread
__global__ void kGridHist(const float* __restrict__ coord, const int* __restrict__ off,
                          int N, int B) {
    int q = blockIdx.x * blockDim.x + threadIdx.x;
    int i0 = q * 4;
    if (i0 >= N) return;
    int G = d_G;
    if (i0 + 3 < N) {
        const float4* c4 = reinterpret_cast<const float4*>(coord) + (size_t)q * 3;
        float4 v0 = __ldg(c4), v1 = __ldg(c4 + 1), v2 = __ldg(c4 + 2);
        int b[4];
        b[0] = batchOf(i0, off, B); b[3] = batchOf(i0 + 3, off, B);
        if (b[0] == b[3]) { b[1] = b[0]; b[2] = b[0]; }
        else { b[1] = batchOf(i0 + 1, off, B); b[2] = batchOf(i0 + 2, off, B); }
        float xs[4] = { v0.x, v0.w, v1.z, v2.y };
        float ys[4] = { v0.y, v1.x, v1.w, v2.z };
        float zs[4] = { v0.z, v1.y, v2.x, v2.w };
        int keys[4];
        #pragma unroll
        for (int k = 0; k < 4; k++) {
            float sx = d_start[3 * b[k] + 0];
            float sy = d_start[3 * b[k] + 1];
            float sz = d_start[3 * b[k] + 2];
            int gx = gridKey(xs[k], sx, G);
            int gy = gridKey(ys[k], sy, G);
            int gz = gridKey(zs[k], sz, G);
            keys[k] = ((b[k] * G + gx) * G + gy) * G + gz;
        }
        reinterpret_cast<int4*>(d_ckey)[q] = make_int4(keys[0], keys[1], keys[2], keys[3]);
        #pragma unroll
        for (int k = 0; k < 4; k++) atomicAdd(&d_voxCount[keys[k]], 1u);
    } else {
        for (int i = i0; i < N; i++) {
            int b = batchOf(i, off, B);
            int gx = gridKey(__ldg(coord + 3 * i + 0), d_start[3 * b + 0], G);
            int gy = gridKey(__ldg(coord + 3 * i + 1), d_start[3 * b + 1], G);
            int gz = gridKey(__ldg(coord + 3 * i + 2), d_start[3 * b + 2], G);
            int key = ((b * G + gx) * G + gy) * G + gz;
            d_ckey[i] = key;
            atomicAdd(&d_voxCount[key], 1u);
        }
    }
}

// single-pass rank with decoupled lookback (CUB-style)
__global__ void __launch_bounds__(256) kRankLB(float* __restrict__ out, int N, int B) {
    __shared__ unsigned sChunk, sPrefix, sTotal;
    __shared__ unsigned warpS[8], wexcl[8];
    const unsigned full = 0xFFFFFFFFu;
    const int nChunks = d_nChunks;
    const int G3 = d_G3;
    float* out_no = out + 3 * N;
    float* out_counts = out + 3 * N + B;
    while (true) {
        if (threadIdx.x == 0) sChunk = atomicAdd(&d_ticket, 1u);
        __syncthreads();
        unsigned chunk = sChunk;
        if (chunk >= (unsigned)nChunks) return;
        int keyBase = (int)chunk * CHUNK;
        unsigned cnts[16]; unsigned tot = 0;
        const uint4* p = reinterpret_cast<const uint4*>(d_voxCount + keyBase)
                         + threadIdx.x * 4;
        #pragma unroll
        for (int k = 0; k < 4; k++) {
            uint4 v = p[k];
            cnts[4 * k + 0] = v.x; cnts[4 * k + 1] = v.y;
            cnts[4 * k + 2] = v.z; cnts[4 * k + 3] = v.w;
            tot += (v.x != 0u) + (v.y != 0u) + (v.z != 0u) + (v.w != 0u);
        }
        int lane = threadIdx.x & 31, wid = threadIdx.x >> 5;
        unsigned incl = tot;
        #pragma unroll
        for (int o = 1; o < 32; o <<= 1) {
            unsigned a = __shfl_up_sync(full, incl, o);
            if (lane >= o) incl += a;
        }
        if (lane == 31) warpS[wid] = incl;
        __syncthreads();
        if (threadIdx.x == 0) {
            unsigned run = 0;
            #pragma unroll
            for (int w = 0; w < 8; w++) { unsigned v = warpS[w]; wexcl[w] = run; run += v; }
            sTotal = run;
            if (chunk == 0) { atomicExch(&d_tileStatus[0], ST_INC | run); sPrefix = 0u; }
            else            atomicExch(&d_tileStatus[chunk], ST_AGG | run);
        }
        __syncthreads();
        if (chunk != 0 && wid == 0) {
            unsigned prefix = 0; int wbase = (int)chunk;
            while (true) {
                int j = wbase - 1 - lane;
                unsigned st = (j >= 0) ? *((volatile unsigned*)&d_tileStatus[j]) : ST_INC;
                if (!__all_sync(full, st != 0u)) continue;   // some tile not ready
                unsigned incmask = __ballot_sync(full, (st & ST_INC) != 0u);
                unsigned v;
                if (incmask) {
                    int closest = __ffs(incmask) - 1;        // nearest predecessor w/ INC
                    v = (lane <= closest) ? (st & VALMASK) : 0u;
                } else {
                    v = st & VALMASK;
                }
                #pragma unroll
                for (int o = 16; o > 0; o >>= 1) v += __shfl_down_sync(full, v, o);
                prefix += __shfl_sync(full, v, 0);
                if (incmask) break;
                wbase -= 32;
            }
            if (lane == 0) {
                sPrefix = prefix;
                atomicExch(&d_tileStatus[chunk], ST_INC | (prefix + sTotal));
            }
        }
        __syncthreads();
        unsigned rank = sPrefix + wexcl[wid] + (incl - tot);
        int key0 = keyBase + threadIdx.x * 16;
        int b0 = key0 / G3;
        int kb = (b0 + 1) * G3 - 1;      // only possible batch boundary in range
        int key = key0;
        #pragma unroll
        for (int k = 0; k < 16; k++, key++) {
            unsigned c = cnts[k];
            unsigned occ = (c != 0u) ? 1u : 0u;
            if (occ) {
                d_voxCount[key] = rank;                 // count -> rank
                out_counts[rank] = (float)c;
            }
            if (key == kb && b0 < B) out_no[b0] = (float)(rank + occ);
            rank += occ;
        }
        __syncthreads();                                // warpS/wexcl reuse
    }
}

__global__ void kScatter(const float* __restrict__ coord, float* __restrict__ out,
                         int N) {
    int q = blockIdx.x * blockDim.x + threadIdx.x;
    int i0 = q * 4;
    if (i0 >= N) return;
    if (i0 + 3 < N) {
        int4 kk = __ldg(reinterpret_cast<const int4*>(d_ckey) + q);
        const float4* c4 = reinterpret_cast<const float4*>(coord) + (size_t)q * 3;
        float4 v0 = __ldg(c4), v1 = __ldg(c4 + 1), v2 = __ldg(c4 + 2);
        unsigned r0 = d_voxCount[kk.x], r1 = d_voxCount[kk.y];
        unsigned r2 = d_voxCount[kk.z], r3 = d_voxCount[kk.w];
        atomicAdd(&out[3 * r0 + 0], v0.x); atomicAdd(&out[3 * r0 + 1], v0.y); atomicAdd(&out[3 * r0 + 2], v0.z);
        atomicAdd(&out[3 * r1 + 0], v0.w); atomicAdd(&out[3 * r1 + 1], v1.x); atomicAdd(&out[3 * r1 + 2], v1.y);
        atomicAdd(&out[3 * r2 + 0], v1.z); atomicAdd(&out[3 * r2 + 1], v1.w); atomicAdd(&out[3 * r2 + 2], v2.x);
        atomicAdd(&out[3 * r3 + 0], v2.y); atomicAdd(&out[3 * r3 + 1], v2.z); atomicAdd(&out[3 * r3 + 2], v2.w);
    } else {
        for (int i = i0; i < N; i++) {
            unsigned r = d_voxCount[d_ckey[i]];
            atomicAdd(&out[3 * r + 0], __ldg(coord + 3 * i + 0));
            atomicAdd(&out[3 * r + 1], __ldg(coord + 3 * i + 1));
            atomicAdd(&out[3 * r + 2], __ldg(coord + 3 * i + 2));
        }
    }
}

__global__ void kFinalize(float* __restrict__ out, int N, int B) {
    int q = blockIdx.x * blockDim.x + threadIdx.x;
    int r0 = q * 4;
    if (r0 >= N) return;
    const float* cc = out + 3 * N + B;
    if (r0 + 3 < N) {
        float c0 = __ldg(cc + r0), c1 = __ldg(cc + r0 + 1);
        float c2 = __ldg(cc + r0 + 2), c3 = __ldg(cc + r0 + 3);
        float4* p = reinterpret_cast<float4*>(out) + (size_t)q * 3;
        float4 v0 = p[0], v1 = p[1], v2 = p[2];
        v0.x = c0 > 0.f ? __fdiv_rn(v0.x, c0) : 0.f;
        v0.y = c0 > 0.f ? __fdiv_rn(v0.y, c0) : 0.f;
        v0.z = c0 > 0.f ? __fdiv_rn(v0.z, c0) : 0.f;
        v0.w = c1 > 0.f ? __fdiv_rn(v0.w, c1) : 0.f;
        v1.x = c1 > 0.f ? __fdiv_rn(v1.x, c1) : 0.f;
        v1.y = c1 > 0.f ? __fdiv_rn(v1.y, c1) : 0.f;
        v1.z = c2 > 0.f ? __fdiv_rn(v1.z, c2) : 0.f;
        v1.w = c2 > 0.f ? __fdiv_rn(v1.w, c2) : 0.f;
        v2.x = c2 > 0.f ? __fdiv_rn(v2.x, c2) : 0.f;
        v2.y = c3 > 0.f ? __fdiv_rn(v2.y, c3) : 0.f;
        v2.z = c3 > 0.f ? __fdiv_rn(v2.z, c3) : 0.f;
        v2.w = c3 > 0.f ? __fdiv_rn(v2.w, c3) : 0.f;
        p[0] = v0; p[1] = v1; p[2] = v2;
    } else {
        for (int r = r0; r < N; r++) {
            float c = __ldg(cc + r);
            if (c > 0.f) {
                out[3 * r + 0] = __fdiv_rn(out[3 * r + 0], c);
                out[3 * r + 1] = __fdiv_rn(out[3 * r + 1], c);
                out[3 * r + 2] = __fdiv_rn(out[3 * r + 2], c);
            }
        }
    }
}

extern "C" void kernel_launch(void* const* d_in, const int* in_sizes, int n_in,
                              void* d_out, int out_size) {
    const float* coord  = (const float*)d_in[0];
    const int*   offset = (const int*)d_in[1];
    int N = in_sizes[0] / 3;
    int B = in_sizes[1];
    float* out = (float*)d_out;

    int nb8 = (int)((N + 8LL * 256 - 1) / (8 * 256));
    int nbq = (int)((N + 4LL * 256 - 1) / (4 * 256));

    kInit<<<(3 * B + 255) / 256, 256>>>(3 * B);
    kMinMax<<<nb8, 256>>>(coord, offset, N, B);
    kSetup<<<1, 256>>>(B);
    kZeroAll<<<4096, 256>>>(out, out_size);
    kGridHist<<<nbq, 256>>>(coord, offset, N, B);
    kRankLB<<<1184, 256>>>(out, N, B);
    kScatter<<<nbq, 256>>>(coord, out, N);
    kFinalize<<<nbq, 256>>>(out, N, B);
}

// round 9
// speedup vs baseline: 2.2724x; 1.0028x over previous
#include <cuda_runtime.h>

// Voxel-grid mean sampling (reference-exact construction):
//   batch = searchsorted(offset, i, right); start = per-batch min(coord)
//   grid  = floor((coord - start[batch]) * 20.0f)   // == XLA's /0.05 rewrite
//   G     = max(grid)+1 ; key = ((b*G+gx)*G+gy)*G+gz ; voxels in ascending key order
// Outputs (float32): [0,3N) n_p means, [3N,3N+B) n_o cumsum voxels/batch,
// [3N+B,4N+B) counts (zero-padded).

#define CHUNK     4096
#define MAXKEYS   (1 << 26)
#define MAXCHUNKS (MAXKEYS / CHUNK)
#define MAXB      256
#define INV_VOXEL 20.0f        // RN(1/0.05f) == 20.0f exactly
#define ST_AGG    (1u << 30)
#define ST_INC    (2u << 30)
#define VALMASK   ((1u << 30) - 1u)

__device__ unsigned d_voxCount[MAXKEYS];   // histogram, then rank per key
__device__ unsigned d_tileStatus[MAXCHUNKS];
__device__ unsigned d_minMapped[MAXB * 3];
__device__ unsigned d_maxMapped[MAXB * 3];
__device__ float    d_start[MAXB * 3];
__device__ int      d_G, d_G3, d_keySpacePad, d_nChunks;
__device__ int      d_nVox;
__device__ unsigned d_ticket;

__device__ __forceinline__ unsigned fmap(float f) {
    unsigned u = __float_as_uint(f);
    return (u & 0x80000000u) ? ~u : (u | 0x80000000u);
}
__device__ __forceinline__ float funmap(unsigned m) {
    unsigned u = (m & 0x80000000u) ? (m & 0x7FFFFFFFu) : ~m;
    return __uint_as_float(u);
}
// first b with offset[b] > i (searchsorted right)
__device__ __forceinline__ int batchOf(int i, const int* __restrict__ off, int B) {
    int lo = 0, hi = B;
    while (lo < hi) {
        int mid = (lo + hi) >> 1;
        if (__ldg(off + mid) <= i) lo = mid + 1; else hi = mid;
    }
    return lo;
}
__device__ __forceinline__ int gridKey(float c, float s, int G) {
    int g = (int)floorf((c - s) * INV_VOXEL);
    return min(max(g, 0), G - 1);
}

__global__ void kInit(int n) {
    int i = blockIdx.x * blockDim.x + threadIdx.x;
    if (i < n) { d_minMapped[i] = 0xFFFFFFFFu; d_maxMapped[i] = 0u; }
}

// per-batch min AND max, 8 points/thread, float4 loads
__global__ void kMinMax(const float* __restrict__ coord, const int* __restrict__ off,
                        int N, int B) {
    const unsigned full = 0xFFFFFFFFu;
    int t = blockIdx.x * blockDim.x + threadIdx.x;
    long long base = (long long)t * 8;
    if (base >= N) return;
    int i0 = (int)base;
    int cnt = min(8, N - i0);
    int bf = batchOf(i0, off, B);
    int bl = batchOf(i0 + cnt - 1, off, B);
    if (bf != bl) {   // rare: spans a batch boundary -> per-point atomics
        for (int i = i0; i < i0 + cnt; i++) {
            int b = batchOf(i, off, B);
            #pragma unroll
            for (int ax = 0; ax < 3; ax++) {
                float v = __ldg(coord + 3 * i + ax);
                atomicMin(&d_minMapped[3 * b + ax], fmap(v));
                atomicMax(&d_maxMapped[3 * b + ax], fmap(v));
            }
        }
        return;
    }
    float mn[3] = { 3.4e38f, 3.4e38f, 3.4e38f };
    float mx[3] = { -3.4e38f, -3.4e38f, -3.4e38f };
    if (cnt == 8) {
        const float4* p = reinterpret_cast<const float4*>(coord + (size_t)i0 * 3);
        #pragma unroll
        for (int k = 0; k < 6; k++) {
            float4 v = __ldg(p + k);
            float a[4] = { v.x, v.y, v.z, v.w };
            #pragma unroll
            for (int j = 0; j < 4; j++) {
                int ax = (4 * k + j) % 3;   // compile-time
                mn[ax] = fminf(mn[ax], a[j]);
                mx[ax] = fmaxf(mx[ax], a[j]);
            }
        }
    } else {
        for (int i = i0; i < i0 + cnt; i++) {
            #pragma unroll
            for (int ax = 0; ax < 3; ax++) {
                float v = __ldg(coord + 3 * i + ax);
                mn[ax] = fminf(mn[ax], v);
                mx[ax] = fmaxf(mx[ax], v);
            }
        }
    }
    unsigned act = __activemask();
    if (act == full) {
        int b0 = __shfl_sync(full, bf, 0);
        if (__all_sync(full, bf == b0)) {
            #pragma unroll
            for (int o = 16; o > 0; o >>= 1) {
                #pragma unroll
                for (int ax = 0; ax < 3; ax++) {
                    mn[ax] = fminf(mn[ax], __shfl_down_sync(full, mn[ax], o));
                    mx[ax] = fmaxf(mx[ax], __shfl_down_sync(full, mx[ax], o));
                }
            }
            if ((threadIdx.x & 31) == 0) {
                #pragma unroll
                for (int ax = 0; ax < 3; ax++) {
                    atomicMin(&d_minMapped[3 * bf + ax], fmap(mn[ax]));
                    atomicMax(&d_maxMapped[3 * bf + ax], fmap(mx[ax]));
                }
            }
            return;
        }
    }
    #pragma unroll
    for (int ax = 0; ax < 3; ax++) {
        atomicMin(&d_minMapped[3 * bf + ax], fmap(mn[ax]));
        atomicMax(&d_maxMapped[3 * bf + ax], fmap(mx[ax]));
    }
}

// start[], G, G3, chunk geometry, ticket reset
__global__ void kSetup(int B) {
    __shared__ int sm[256];
    int m = 0;
    for (int b = threadIdx.x; b < B; b += 256) {
        #pragma unroll
        for (int ax = 0; ax < 3; ax++) {
            float s = funmap(d_minMapped[3 * b + ax]);
            float M = funmap(d_maxMapped[3 * b + ax]);
            d_start[3 * b + ax] = s;
            int e = (int)floorf((M - s) * INV_VOXEL);  // == max per-point grid idx
            m = max(m, e);
        }
    }
    sm[threadIdx.x] = m; __syncthreads();
    for (int o = 128; o > 0; o >>= 1) {
        if (threadIdx.x < o) sm[threadIdx.x] = max(sm[threadIdx.x], sm[threadIdx.x + o]);
        __syncthreads();
    }
    if (threadIdx.x == 0) {
        int G = sm[0] + 1;
        long long ks = (long long)B * G * G * G;
        if (ks > MAXKEYS) ks = MAXKEYS;
        int nc = (int)((ks + CHUNK - 1) / CHUNK);
        d_G = G; d_G3 = G * G * G;
        d_nChunks = nc; d_keySpacePad = nc * CHUNK;
        d_ticket = 0u;
    }
}

__global__ void kZeroAll(float* __restrict__ out, int outN) {
    int idx = blockIdx.x * blockDim.x + threadIdx.x;
    int stride = gridDim.x * blockDim.x;
    uint4 z = make_uint4(0u, 0u, 0u, 0u);
    int n4 = d_keySpacePad >> 2;            // pad multiple of 4096
    uint4* p = reinterpret_cast<uint4*>(d_voxCount);
    for (int k = idx; k < n4; k += stride) p[k] = z;
    int nc = d_nChunks;
    for (int k = idx; k < nc; k += stride) d_tileStatus[k] = 0u;
    int o4 = outN >> 2;
    uint4* q = reinterpret_cast<uint4*>(out);
    for (int k = idx; k < o4; k += stride) q[k] = z;
    for (int k = (o4 << 2) + idx; k < outN; k += stride) out[k] = 0.0f;
}

// fused grid + histogram, 8 points/thread, key recomputed later in scatter
__global__ void kGridHist(const float* __restrict__ coord, const int* __restrict__ off,
                          int N, int B) {
    int t = blockIdx.x * blockDim.x + threadIdx.x;
    long long base = (long long)t * 8;
    if (base >= N) return;
    int i0 = (int)base;
    int G = d_G;
    if (i0 + 7 < N) {
        const float4* c4 = reinterpret_cast<const float4*>(coord + (size_t)i0 * 3);
        float a[24];
        #pragma unroll
        for (int k = 0; k < 6; k++) {
            float4 v = __ldg(c4 + k);
            a[4 * k + 0] = v.x; a[4 * k + 1] = v.y;
            a[4 * k + 2] = v.z; a[4 * k + 3] = v.w;
        }
        int bf = batchOf(i0, off, B);
        int bl = batchOf(i0 + 7, off, B);
        int keys[8];
        #pragma unroll
        for (int k = 0; k < 8; k++) {
            int b = (bf == bl) ? bf : batchOf(i0 + k, off, B);
            float sx = d_start[3 * b + 0];
            float sy = d_start[3 * b + 1];
            float sz = d_start[3 * b + 2];
            int gx = gridKey(a[3 * k + 0], sx, G);
            int gy = gridKey(a[3 * k + 1], sy, G);
            int gz = gridKey(a[3 * k + 2], sz, G);
            keys[k] = ((b * G + gx) * G + gy) * G + gz;
        }
        #pragma unroll
        for (int k = 0; k < 8; k++) atomicAdd(&d_voxCount[keys[k]], 1u);
    } else {
        for (int i = i0; i < N; i++) {
            int b = batchOf(i, off, B);
            int gx = gridKey(__ldg(coord + 3 * i + 0), d_start[3 * b + 0], G);
            int gy = gridKey(__ldg(coord + 3 * i + 1), d_start[3 * b + 1], G);
            int gz = gridKey(__ldg(coord + 3 * i + 2), d_start[3 * b + 2], G);
            atomicAdd(&d_voxCount[((b * G + gx) * G + gy) * G + gz], 1u);
        }
    }
}

// single-pass rank with decoupled lookback (CUB-style)
__global__ void __launch_bounds__(256) kRankLB(float* __restrict__ out, int N, int B) {
    __shared__ unsigned sChunk, sPrefix, sTotal;
    __shared__ unsigned warpS[8], wexcl[8];
    const unsigned full = 0xFFFFFFFFu;
    const int nChunks = d_nChunks;
    const int G3 = d_G3;
    float* out_no = out + 3 * N;
    float* out_counts = out + 3 * N + B;
    while (true) {
        if (threadIdx.x == 0) sChunk = atomicAdd(&d_ticket, 1u);
        __syncthreads();
        unsigned chunk = sChunk;
        if (chunk >= (unsigned)nChunks) return;
        int keyBase = (int)chunk * CHUNK;
        unsigned cnts[16]; unsigned tot = 0;
        const uint4* p = reinterpret_cast<const uint4*>(d_voxCount + keyBase)
                         + threadIdx.x * 4;
        #pragma unroll
        for (int k = 0; k < 4; k++) {
            uint4 v = p[k];
            cnts[4 * k + 0] = v.x; cnts[4 * k + 1] = v.y;
            cnts[4 * k + 2] = v.z; cnts[4 * k + 3] = v.w;
            tot += (v.x != 0u) + (v.y != 0u) + (v.z != 0u) + (v.w != 0u);
        }
        int lane = threadIdx.x & 31, wid = threadIdx.x >> 5;
        unsigned incl = tot;
        #pragma unroll
        for (int o = 1; o < 32; o <<= 1) {
            unsigned a = __shfl_up_sync(full, incl, o);
            if (lane >= o) incl += a;
        }
        if (lane == 31) warpS[wid] = incl;
        __syncthreads();
        if (threadIdx.x == 0) {
            unsigned run = 0;
            #pragma unroll
            for (int w = 0; w < 8; w++) { unsigned v = warpS[w]; wexcl[w] = run; run += v; }
            sTotal = run;
            if (chunk == 0) { atomicExch(&d_tileStatus[0], ST_INC | run); sPrefix = 0u; }
            else            atomicExch(&d_tileStatus[chunk], ST_AGG | run);
        }
        __syncthreads();
        if (chunk != 0 && wid == 0) {
            unsigned prefix = 0; int wbase = (int)chunk;
            while (true) {
                int j = wbase - 1 - lane;
                unsigned st = (j >= 0) ? *((volatile unsigned*)&d_tileStatus[j]) : ST_INC;
                if (!__all_sync(full, st != 0u)) continue;   // some tile not ready
                unsigned incmask = __ballot_sync(full, (st & ST_INC) != 0u);
                unsigned v;
                if (incmask) {
                    int closest = __ffs(incmask) - 1;        // nearest predecessor w/ INC
                    v = (lane <= closest) ? (st & VALMASK) : 0u;
                } else {
                    v = st & VALMASK;
                }
                #pragma unroll
                for (int o = 16; o > 0; o >>= 1) v += __shfl_down_sync(full, v, o);
                prefix += __shfl_sync(full, v, 0);
                if (incmask) break;
                wbase -= 32;
            }
            if (lane == 0) {
                sPrefix = prefix;
                atomicExch(&d_tileStatus[chunk], ST_INC | (prefix + sTotal));
            }
        }
        __syncthreads();
        if (chunk == (unsigned)(nChunks - 1) && threadIdx.x == 0)
            d_nVox = (int)(sPrefix + sTotal);               // total voxel count
        unsigned rank = sPrefix + wexcl[wid] + (incl - tot);
        int key0 = keyBase + threadIdx.x * 16;
        int b0 = key0 / G3;
        int kb = (b0 + 1) * G3 - 1;      // only possible batch boundary in range
        int key = key0;
        #pragma unroll
        for (int k = 0; k < 16; k++, key++) {
            unsigned c = cnts[k];
            unsigned occ = (c != 0u) ? 1u : 0u;
            if (occ) {
                d_voxCount[key] = rank;                 // count -> rank
                out_counts[rank] = (float)c;
            }
            if (key == kb && b0 < B) out_no[b0] = (float)(rank + occ);
            rank += occ;
        }
        __syncthreads();                                // warpS/wexcl reuse
    }
}

// scatter: recompute key (bit-identical), gather rank, atomicAdd coords
__global__ void kScatter(const float* __restrict__ coord, const int* __restrict__ off,
                         float* __restrict__ out, int N, int B) {
    int t = blockIdx.x * blockDim.x + threadIdx.x;
    long long base = (long long)t * 8;
    if (base >= N) return;
    int i0 = (int)base;
    int G = d_G;
    if (i0 + 7 < N) {
        const float4* c4 = reinterpret_cast<const float4*>(coord + (size_t)i0 * 3);
        float a[24];
        #pragma unroll
        for (int k = 0; k < 6; k++) {
            float4 v = __ldg(c4 + k);
            a[4 * k + 0] = v.x; a[4 * k + 1] = v.y;
            a[4 * k + 2] = v.z; a[4 * k + 3] = v.w;
        }
        int bf = batchOf(i0, off, B);
        int bl = batchOf(i0 + 7, off, B);
        unsigned r[8];
        #pragma unroll
        for (int k = 0; k < 8; k++) {
            int b = (bf == bl) ? bf : batchOf(i0 + k, off, B);
            float sx = d_start[3 * b + 0];
            float sy = d_start[3 * b + 1];
            float sz = d_start[3 * b + 2];
            int gx = gridKey(a[3 * k + 0], sx, G);
            int gy = gridKey(a[3 * k + 1], sy, G);
            int gz = gridKey(a[3 * k + 2], sz, G);
            r[k] = d_voxCount[((b * G + gx) * G + gy) * G + gz];
        }
        #pragma unroll
        for (int k = 0; k < 8; k++) {
            atomicAdd(&out[3 * r[k] + 0], a[3 * k + 0]);
            atomicAdd(&out[3 * r[k] + 1], a[3 * k + 1]);
            atomicAdd(&out[3 * r[k] + 2], a[3 * k + 2]);
        }
    } else {
        for (int i = i0; i < N; i++) {
            int b = batchOf(i, off, B);
            float x = __ldg(coord + 3 * i + 0);
            float y = __ldg(coord + 3 * i + 1);
            float z = __ldg(coord + 3 * i + 2);
            int gx = gridKey(x, d_start[3 * b + 0], G);
            int gy = gridKey(y, d_start[3 * b + 1], G);
            int gz = gridKey(z, d_start[3 * b + 2], G);
            unsigned r = d_voxCount[((b * G + gx) * G + gy) * G + gz];
            atomicAdd(&out[3 * r + 0], x);
            atomicAdd(&out[3 * r + 1], y);
            atomicAdd(&out[3 * r + 2], z);
        }
    }
}

// divide only the nVox live rows (rest already zero)
__global__ void kFinalize(float* __restrict__ out, int N, int B) {
    int nVox = d_nVox;
    int q = blockIdx.x * blockDim.x + threadIdx.x;
    int r0 = q * 4;
    if (r0 >= nVox) return;
    const float* cc = out + 3 * N + B;
    if (r0 + 3 < nVox) {
        float c0 = __ldg(cc + r0), c1 = __ldg(cc + r0 + 1);
        float c2 = __ldg(cc + r0 + 2), c3 = __ldg(cc + r0 + 3);
        float4* p = reinterpret_cast<float4*>(out) + (size_t)q * 3;
        float4 v0 = p[0], v1 = p[1], v2 = p[2];
        v0.x = __fdiv_rn(v0.x, c0); v0.y = __fdiv_rn(v0.y, c0); v0.z = __fdiv_rn(v0.z, c0);
        v0.w = __fdiv_rn(v0.w, c1); v1.x = __fdiv_rn(v1.x, c1); v1.y = __fdiv_rn(v1.y, c1);
        v1.z = __fdiv_rn(v1.z, c2); v1.w = __fdiv_rn(v1.w, c2); v2.x = __fdiv_rn(v2.x, c2);
        v2.y = __fdiv_rn(v2.y, c3); v2.z = __fdiv_rn(v2.z, c3); v2.w = __fdiv_rn(v2.w, c3);
        p[0] = v0; p[1] = v1; p[2] = v2;
    } else {
        for (int r = r0; r < nVox; r++) {
            float c = __ldg(cc + r);
            out[3 * r + 0] = __fdiv_rn(out[3 * r + 0], c);
            out[3 * r + 1] = __fdiv_rn(out[3 * r + 1], c);
            out[3 * r + 2] = __fdiv_rn(out[3 * r + 2], c);
        }
    }
}

extern "C" void kernel_launch(void* const* d_in, const int* in_sizes, int n_in,
                              void* d_out, int out_size) {
    const float* coord  = (const float*)d_in[0];
    const int*   offset = (const int*)d_in[1];
    int N = in_sizes[0] / 3;
    int B = in_sizes[1];
    float* out = (float*)d_out;

    int nb8 = (int)((N + 8LL * 256 - 1) / (8 * 256));
    int nbq = (int)((N + 4LL * 256 - 1) / (4 * 256));

    kInit<<<(3 * B + 255) / 256, 256>>>(3 * B);
    kMinMax<<<nb8, 256>>>(coord, offset, N, B);
    kSetup<<<1, 256>>>(B);
    kZeroAll<<<4096, 256>>>(out, out_size);
    kGridHist<<<nb8, 256>>>(coord, offset, N, B);
    kRankLB<<<1184, 256>>>(out, N, B);
    kScatter<<<nb8, 256>>>(coord, offset, out, N, B);
    kFinalize<<<nbq, 256>>>(out, N, B);
}

// round 13
// speedup vs baseline: 2.4114x; 1.0611x over previous
#include <cuda_runtime.h>

// Voxel-grid mean sampling (reference-exact construction):
//   batch = searchsorted(offset, i, right); start = per-batch min(coord)
//   grid  = floor((coord - start[batch]) * 20.0f)   // == XLA's /0.05 rewrite
//   G     = max(grid)+1 ; key = ((b*G+gx)*G+gy)*G+gz ; voxels in ascending key order
// Outputs (float32): [0,3N) n_p means, [3N,3N+B) n_o cumsum voxels/batch,
// [3N+B,4N+B) counts (zero-padded).

#define CHUNK     16384
#define RTHREADS  512
#define CELLS_PT  32            // CHUNK / RTHREADS
#define MAXKEYS   (1 << 26)
#define MAXCHUNKS (MAXKEYS / CHUNK)
#define MAXN      (1 << 23)
#define MAXB      256
#define INV_VOXEL 20.0f         // RN(1/0.05f) == 20.0f exactly
#define ST_AGG    (1u << 30)
#define ST_INC    (2u << 30)
#define VALMASK   ((1u << 30) - 1u)

__device__ unsigned d_voxCount[MAXKEYS];   // histogram, then rank per key
__device__ float4   d_scratch[MAXN];       // per-voxel {sumx,sumy,sumz,count}
__device__ unsigned d_tileStatus[MAXCHUNKS];
__device__ unsigned d_minMapped[MAXB * 3];
__device__ unsigned d_maxMapped[MAXB * 3];
__device__ float    d_start[MAXB * 3];
__device__ int      d_G, d_G3, d_keySpacePad, d_nChunks;
__device__ int      d_nVox;
__device__ unsigned d_ticket;

__device__ __forceinline__ unsigned fmap(float f) {
    unsigned u = __float_as_uint(f);
    return (u & 0x80000000u) ? ~u : (u | 0x80000000u);
}
__device__ __forceinline__ float funmap(unsigned m) {
    unsigned u = (m & 0x80000000u) ? (m & 0x7FFFFFFFu) : ~m;
    return __uint_as_float(u);
}
// first b with offset[b] > i (searchsorted right)
__device__ __forceinline__ int batchOf(int i, const int* __restrict__ off, int B) {
    int lo = 0, hi = B;
    while (lo < hi) {
        int mid = (lo + hi) >> 1;
        if (__ldg(off + mid) <= i) lo = mid + 1; else hi = mid;
    }
    return lo;
}
__device__ __forceinline__ int gridKey(float c, float s, int G) {
    int g = (int)floorf((c - s) * INV_VOXEL);
    return min(max(g, 0), G - 1);
}
__device__ __forceinline__ void red4(float4* p, float x, float y, float z, float w) {
    asm volatile("red.global.add.v4.f32 [%0], {%1,%2,%3,%4};"
                 :: "l"(p), "f"(x), "f"(y), "f"(z), "f"(w) : "memory");
}

__global__ void kInit(int n) {
    int i = blockIdx.x * blockDim.x + threadIdx.x;
    if (i < n) { d_minMapped[i] = 0xFFFFFFFFu; d_maxMapped[i] = 0u; }
}

// per-batch min AND max, 8 points/thread, float4 loads
__global__ void kMinMax(const float* __restrict__ coord, const int* __restrict__ off,
                        int N, int B) {
    const unsigned full = 0xFFFFFFFFu;
    int t = blockIdx.x * blockDim.x + threadIdx.x;
    long long base = (long long)t * 8;
    if (base >= N) return;
    int i0 = (int)base;
    int cnt = min(8, N - i0);
    int bf = batchOf(i0, off, B);
    int bl = batchOf(i0 + cnt - 1, off, B);
    if (bf != bl) {   // rare: spans a batch boundary -> per-point atomics
        for (int i = i0; i < i0 + cnt; i++) {
            int b = batchOf(i, off, B);
            #pragma unroll
            for (int ax = 0; ax < 3; ax++) {
                float v = __ldg(coord + 3 * i + ax);
                atomicMin(&d_minMapped[3 * b + ax], fmap(v));
                atomicMax(&d_maxMapped[3 * b + ax], fmap(v));
            }
        }
        return;
    }
    float mn[3] = { 3.4e38f, 3.4e38f, 3.4e38f };
    float mx[3] = { -3.4e38f, -3.4e38f, -3.4e38f };
    if (cnt == 8) {
        const float4* p = reinterpret_cast<const float4*>(coord + (size_t)i0 * 3);
        #pragma unroll
        for (int k = 0; k < 6; k++) {
            float4 v = __ldg(p + k);
            float a[4] = { v.x, v.y, v.z, v.w };
            #pragma unroll
            for (int j = 0; j < 4; j++) {
                int ax = (4 * k + j) % 3;   // compile-time
                mn[ax] = fminf(mn[ax], a[j]);
                mx[ax] = fmaxf(mx[ax], a[j]);
            }
        }
    } else {
        for (int i = i0; i < i0 + cnt; i++) {
            #pragma unroll
            for (int ax = 0; ax < 3; ax++) {
                float v = __ldg(coord + 3 * i + ax);
                mn[ax] = fminf(mn[ax], v);
                mx[ax] = fmaxf(mx[ax], v);
            }
        }
    }
    unsigned act = __activemask();
    if (act == full) {
        int b0 = __shfl_sync(full, bf, 0);
        if (__all_sync(full, bf == b0)) {
            #pragma unroll
            for (int o = 16; o > 0; o >>= 1) {
                #pragma unroll
                for (int ax = 0; ax < 3; ax++) {
                    mn[ax] = fminf(mn[ax], __shfl_down_sync(full, mn[ax], o));
                    mx[ax] = fmaxf(mx[ax], __shfl_down_sync(full, mx[ax], o));
                }
            }
            if ((threadIdx.x & 31) == 0) {
                #pragma unroll
                for (int ax = 0; ax < 3; ax++) {
                    atomicMin(&d_minMapped[3 * bf + ax], fmap(mn[ax]));
                    atomicMax(&d_maxMapped[3 * bf + ax], fmap(mx[ax]));
                }
            }
            return;
        }
    }
    #pragma unroll
    for (int ax = 0; ax < 3; ax++) {
        atomicMin(&d_minMapped[3 * bf + ax], fmap(mn[ax]));
        atomicMax(&d_maxMapped[3 * bf + ax], fmap(mx[ax]));
    }
}

// start[], G, G3, chunk geometry, ticket reset
__global__ void kSetup(int B) {
    __shared__ int sm[256];
    int m = 0;
    for (int b = threadIdx.x; b < B; b += 256) {
        #pragma unroll
        for (int ax = 0; ax < 3; ax++) {
            float s = funmap(d_minMapped[3 * b + ax]);
            float M = funmap(d_maxMapped[3 * b + ax]);
            d_start[3 * b + ax] = s;
            int e = (int)floorf((M - s) * INV_VOXEL);  // == max per-point grid idx
            m = max(m, e);
        }
    }
    sm[threadIdx.x] = m; __syncthreads();
    for (int o = 128; o > 0; o >>= 1) {
        if (threadIdx.x < o) sm[threadIdx.x] = max(sm[threadIdx.x], sm[threadIdx.x + o]);
        __syncthreads();
    }
    if (threadIdx.x == 0) {
        int G = sm[0] + 1;
        long long ks = (long long)B * G * G * G;
        if (ks > MAXKEYS) ks = MAXKEYS;
        int nc = (int)((ks + CHUNK - 1) / CHUNK);
        d_G = G; d_G3 = G * G * G;
        d_nChunks = nc; d_keySpacePad = nc * CHUNK;
        d_ticket = 0u;
    }
}

__global__ void kZeroAll(float* __restrict__ out, int outN) {
    int idx = blockIdx.x * blockDim.x + threadIdx.x;
    int stride = gridDim.x * blockDim.x;
    uint4 z = make_uint4(0u, 0u, 0u, 0u);
    int n4 = d_keySpacePad >> 2;            // pad multiple of CHUNK
    uint4* p = reinterpret_cast<uint4*>(d_voxCount);
    for (int k = idx; k < n4; k += stride) p[k] = z;
    int nc = d_nChunks;
    for (int k = idx; k < nc; k += stride) d_tileStatus[k] = 0u;
    int o4 = outN >> 2;
    uint4* q = reinterpret_cast<uint4*>(out);
    for (int k = idx; k < o4; k += stride) q[k] = z;
    for (int k = (o4 << 2) + idx; k < outN; k += stride) out[k] = 0.0f;
}

// fused grid + histogram, 8 points/thread, key recomputed later in scatter
__global__ void kGridHist(const float* __restrict__ coord, const int* __restrict__ off,
                          int N, int B) {
    int t = blockIdx.x * blockDim.x + threadIdx.x;
    long long base = (long long)t * 8;
    if (base >= N) return;
    int i0 = (int)base;
    int G = d_G;
    if (i0 + 7 < N) {
        const float4* c4 = reinterpret_cast<const float4*>(coord + (size_t)i0 * 3);
        float a[24];
        #pragma unroll
        for (int k = 0; k < 6; k++) {
            float4 v = __ldg(c4 + k);
            a[4 * k + 0] = v.x; a[4 * k + 1] = v.y;
            a[4 * k + 2] = v.z; a[4 * k + 3] = v.w;
        }
        int bf = batchOf(i0, off, B);
        int bl = batchOf(i0 + 7, off, B);
        int keys[8];
        #pragma unroll
        for (int k = 0; k < 8; k++) {
            int b = (bf == bl) ? bf : batchOf(i0 + k, off, B);
            float sx = d_start[3 * b + 0];
            float sy = d_start[3 * b + 1];
            float sz = d_start[3 * b + 2];
            int gx = gridKey(a[3 * k + 0], sx, G);
            int gy = gridKey(a[3 * k + 1], sy, G);
            int gz = gridKey(a[3 * k + 2], sz, G);
            keys[k] = ((b * G + gx) * G + gy) * G + gz;
        }
        #pragma unroll
        for (int k = 0; k < 8; k++) atomicAdd(&d_voxCount[keys[k]], 1u);
    } else {
        for (int i = i0; i < N; i++) {
            int b = batchOf(i, off, B);
            int gx = gridKey(__ldg(coord + 3 * i + 0), d_start[3 * b + 0], G);
            int gy = gridKey(__ldg(coord + 3 * i + 1), d_start[3 * b + 1], G);
            int gz = gridKey(__ldg(coord + 3 * i + 2), d_start[3 * b + 2], G);
            atomicAdd(&d_voxCount[((b * G + gx) * G + gy) * G + gz], 1u);
        }
    }
}

// single-pass rank with decoupled lookback; also zeros this chunk's scratch rows
__global__ void __launch_bounds__(RTHREADS) kRankLB(float* __restrict__ out,
                                                    int N, int B) {
    __shared__ unsigned sChunk, sPrefix, sTotal;
    __shared__ unsigned warpS[RTHREADS / 32], wexcl[RTHREADS / 32];
    const unsigned full = 0xFFFFFFFFu;
    const int nChunks = d_nChunks;
    const int G3 = d_G3;
    float* out_no = out + 3 * N;
    while (true) {
        if (threadIdx.x == 0) sChunk = atomicAdd(&d_ticket, 1u);
        __syncthreads();
        unsigned chunk = sChunk;
        if (chunk >= (unsigned)nChunks) return;
        int keyBase = (int)chunk * CHUNK;
        unsigned cnts[CELLS_PT]; unsigned tot = 0;
        const uint4* p = reinterpret_cast<const uint4*>(d_voxCount + keyBase)
                         + threadIdx.x * (CELLS_PT / 4);
        #pragma unroll
        for (int k = 0; k < CELLS_PT / 4; k++) {
            uint4 v = p[k];
            cnts[4 * k + 0] = v.x; cnts[4 * k + 1] = v.y;
            cnts[4 * k + 2] = v.z; cnts[4 * k + 3] = v.w;
            tot += (v.x != 0u) + (v.y != 0u) + (v.z != 0u) + (v.w != 0u);
        }
        int lane = threadIdx.x & 31, wid = threadIdx.x >> 5;
        unsigned incl = tot;
        #pragma unroll
        for (int o = 1; o < 32; o <<= 1) {
            unsigned a = __shfl_up_sync(full, incl, o);
            if (lane >= o) incl += a;
        }
        if (lane == 31) warpS[wid] = incl;
        __syncthreads();
        if (wid == 0) {                    // scan the 16 warp totals
            unsigned v = (lane < RTHREADS / 32) ? warpS[lane] : 0u;
            unsigned iv = v;
            #pragma unroll
            for (int o = 1; o < 32; o <<= 1) {
                unsigned a = __shfl_up_sync(full, iv, o);
                if (lane >= o) iv += a;
            }
            if (lane < RTHREADS / 32) wexcl[lane] = iv - v;
            if (lane == (RTHREADS / 32) - 1) {
                sTotal = iv;
                if (chunk == 0) { atomicExch(&d_tileStatus[0], ST_INC | iv); sPrefix = 0u; }
                else            atomicExch(&d_tileStatus[chunk], ST_AGG | iv);
            }
        }
        __syncthreads();
        if (chunk != 0 && wid == 0) {
            unsigned prefix = 0; int wbase = (int)chunk;
            while (true) {
                int j = wbase - 1 - lane;
                unsigned st = (j >= 0) ? *((volatile unsigned*)&d_tileStatus[j]) : ST_INC;
                if (!__all_sync(full, st != 0u)) continue;   // some tile not ready
                unsigned incmask = __ballot_sync(full, (st & ST_INC) != 0u);
                unsigned v;
                if (incmask) {
                    int closest = __ffs(incmask) - 1;        // nearest predecessor w/ INC
                    v = (lane <= closest) ? (st & VALMASK) : 0u;
                } else {
                    v = st & VALMASK;
                }
                #pragma unroll
                for (int o = 16; o > 0; o >>= 1) v += __shfl_down_sync(full, v, o);
                prefix += __shfl_sync(full, v, 0);
                if (incmask) break;
                wbase -= 32;
            }
            if (lane == 0) {
                sPrefix = prefix;
                atomicExch(&d_tileStatus[chunk], ST_INC | (prefix + sTotal));
            }
        }
        __syncthreads();
        unsigned cpfx = sPrefix, ctot = sTotal;
        if (chunk == (unsigned)(nChunks - 1) && threadIdx.x == 0)
            d_nVox = (int)(cpfx + ctot);                    // total voxel count
        unsigned rank = cpfx + wexcl[wid] + (incl - tot);
        int key0 = keyBase + threadIdx.x * CELLS_PT;
        int b0 = key0 / G3;
        int kb = (b0 + 1) * G3 - 1;      // only possible batch boundary in range
        int key = key0;
        #pragma unroll
        for (int k = 0; k < CELLS_PT; k++, key++) {
            unsigned c = cnts[k];
            unsigned occ = (c != 0u) ? 1u : 0u;
            if (occ) d_voxCount[key] = rank;                // count -> rank
            if (key == kb && b0 < B) out_no[b0] = (float)(rank + occ);
            rank += occ;
        }
        // zero this chunk's scratch rows [cpfx, cpfx+ctot) for the scatter pass
        float4 z4 = make_float4(0.f, 0.f, 0.f, 0.f);
        for (unsigned i = threadIdx.x; i < ctot; i += RTHREADS)
            d_scratch[cpfx + i] = z4;
        __syncthreads();                                    // smem reuse
    }
}

// scatter: recompute key (bit-identical), gather rank, ONE vector RED per point
__global__ void kScatter(const float* __restrict__ coord, const int* __restrict__ off,
                         int N, int B) {
    int t = blockIdx.x * blockDim.x + threadIdx.x;
    long long base = (long long)t * 8;
    if (base >= N) return;
    int i0 = (int)base;
    int G = d_G;
    if (i0 + 7 < N) {
        const float4* c4 = reinterpret_cast<const float4*>(coord + (size_t)i0 * 3);
        float a[24];
        #pragma unroll
        for (int k = 0; k < 6; k++) {
            float4 v = __ldg(c4 + k);
            a[4 * k + 0] = v.x; a[4 * k + 1] = v.y;
            a[4 * k + 2] = v.z; a[4 * k + 3] = v.w;
        }
        int bf = batchOf(i0, off, B);
        int bl = batchOf(i0 + 7, off, B);
        unsigned r[8];
        #pragma unroll
        for (int k = 0; k < 8; k++) {
            int b = (bf == bl) ? bf : batchOf(i0 + k, off, B);
            float sx = d_start[3 * b + 0];
            float sy = d_start[3 * b + 1];
            float sz = d_start[3 * b + 2];
            int gx = gridKey(a[3 * k + 0], sx, G);
            int gy = gridKey(a[3 * k + 1], sy, G);
            int gz = gridKey(a[3 * k + 2], sz, G);
            r[k] = d_voxCount[((b * G + gx) * G + gy) * G + gz];
        }
        #pragma unroll
        for (int k = 0; k < 8; k++)
            red4(&d_scratch[r[k]], a[3 * k + 0], a[3 * k + 1], a[3 * k + 2], 1.0f);
    } else {
        for (int i = i0; i < N; i++) {
            int b = batchOf(i, off, B);
            float x = __ldg(coord + 3 * i + 0);
            float y = __ldg(coord + 3 * i + 1);
            float z = __ldg(coord + 3 * i + 2);
            int gx = gridKey(x, d_start[3 * b + 0], G);
            int gy = gridKey(y, d_start[3 * b + 1], G);
            int gz = gridKey(z, d_start[3 * b + 2], G);
            unsigned r = d_voxCount[((b * G + gx) * G + gy) * G + gz];
            red4(&d_scratch[r], x, y, z, 1.0f);
        }
    }
}

// means + counts from scratch, only the nVox live rows (rest already zero)
__global__ void kFinalize(float* __restrict__ out, int N, int B) {
    int nVox = d_nVox;
    int q = blockIdx.x * blockDim.x + threadIdx.x;
    int r0 = q * 4;
    if (r0 >= nVox) return;
    float* out_counts = out + 3 * N + B;
    if (r0 + 3 < nVox) {
        float4 s0 = __ldg(d_scratch + r0 + 0);
        float4 s1 = __ldg(d_scratch + r0 + 1);
        float4 s2 = __ldg(d_scratch + r0 + 2);
        float4 s3 = __ldg(d_scratch + r0 + 3);
        float4 v0, v1, v2;
        v0.x = __fdiv_rn(s0.x, s0.w); v0.y = __fdiv_rn(s0.y, s0.w); v0.z = __fdiv_rn(s0.z, s0.w);
        v0.w = __fdiv_rn(s1.x, s1.w); v1.x = __fdiv_rn(s1.y, s1.w); v1.y = __fdiv_rn(s1.z, s1.w);
        v1.z = __fdiv_rn(s2.x, s2.w); v1.w = __fdiv_rn(s2.y, s2.w); v2.x = __fdiv_rn(s2.z, s2.w);
        v2.y = __fdiv_rn(s3.x, s3.w); v2.z = __fdiv_rn(s3.y, s3.w); v2.w = __fdiv_rn(s3.z, s3.w);
        float4* p = reinterpret_cast<float4*>(out) + (size_t)q * 3;
        p[0] = v0; p[1] = v1; p[2] = v2;
        out_counts[r0 + 0] = s0.w; out_counts[r0 + 1] = s1.w;
        out_counts[r0 + 2] = s2.w; out_counts[r0 + 3] = s3.w;
    } else {
        for (int r = r0; r < nVox; r++) {
            float4 s = __ldg(d_scratch + r);
            out[3 * r + 0] = __fdiv_rn(s.x, s.w);
            out[3 * r + 1] = __fdiv_rn(s.y, s.w);
            out[3 * r + 2] = __fdiv_rn(s.z, s.w);
            out_counts[r] = s.w;
        }
    }
}

extern "C" void kernel_launch(void* const* d_in, const int* in_sizes, int n_in,
                              void* d_out, int out_size) {
    const float* coord  = (const float*)d_in[0];
    const int*   offset = (const int*)d_in[1];
    int N = in_sizes[0] / 3;
    int B = in_sizes[1];
    float* out = (float*)d_out;

    int nb8 = (int)((N + 8LL * 256 - 1) / (8 * 256));
    int nbq = (int)((N + 4LL * 256 - 1) / (4 * 256));

    kInit<<<(3 * B + 255) / 256, 256>>>(3 * B);
    kMinMax<<<nb8, 256>>>(coord, offset, N, B);
    kSetup<<<1, 256>>>(B);
    kZeroAll<<<4096, 256>>>(out, out_size);
    kGridHist<<<nb8, 256>>>(coord, offset, N, B);
    kRankLB<<<296, RTHREADS>>>(out, N, B);
    kScatter<<<nb8, 256>>>(coord, offset, N, B);
    kFinalize<<<nbq, 256>>>(out, N, B);
}

// round 16
// speedup vs baseline: 3.6568x; 1.5165x over previous
#include <cuda_runtime.h>

// Voxel-grid mean sampling (reference-exact construction):
//   batch = searchsorted(offset, i, right); start = per-batch min(coord)
//   grid  = floor((coord - start[batch]) * 20.0f)   // == XLA's /0.05 rewrite
//   G     = max(grid)+1 ; key = ((b*G+gx)*G+gy)*G+gz ; voxels in ascending key order
// Occupancy is a bitmap with an interleaved per-word exclusive prefix
// (uint2 {bits, prefix}); per-voxel sums/counts accumulate in a float4
// scratch via one red.global.add.v4.f32 per point.
// Outputs (float32): [0,3N) n_p means, [3N,3N+B) n_o cumsum voxels/batch,
// [3N+B,4N+B) counts (zero-padded).

#define WCHUNK    4096          // bitmap words per rank chunk
#define RT        256
#define WORDS_PT  16            // WCHUNK / RT
#define MAXKEYS   (1 << 26)
#define MAXWORDS  ((MAXKEYS >> 5) + 2)
#define MAXWCH    ((MAXWORDS + WCHUNK - 1) / WCHUNK)
#define MAXWPAD   (MAXWCH * WCHUNK)
#define MAXN      (1 << 23)
#define MAXB      256
#define INV_VOXEL 20.0f         // RN(1/0.05f) == 20.0f exactly
#define ST_AGG    (1u << 30)
#define ST_INC    (2u << 30)
#define VALMASK   ((1u << 30) - 1u)

__device__ uint2    d_occ[MAXWPAD];        // {bitmap word, exclusive prefix}
__device__ float4   d_scratch[MAXN];       // per-voxel {sumx,sumy,sumz,count}
__device__ unsigned d_tileStatus[MAXWCH];
__device__ unsigned d_minMapped[MAXB * 3];
__device__ unsigned d_maxMapped[MAXB * 3];
__device__ float    d_start[MAXB * 3];
__device__ int      d_G, d_G3, d_nWChunks, d_nWordsPad;
__device__ int      d_nVox;
__device__ unsigned d_ticket;

__device__ __forceinline__ unsigned fmap(float f) {
    unsigned u = __float_as_uint(f);
    return (u & 0x80000000u) ? ~u : (u | 0x80000000u);
}
__device__ __forceinline__ float funmap(unsigned m) {
    unsigned u = (m & 0x80000000u) ? (m & 0x7FFFFFFFu) : ~m;
    return __uint_as_float(u);
}
// first b with offset[b] > i (searchsorted right)
__device__ __forceinline__ int batchOf(int i, const int* __restrict__ off, int B) {
    int lo = 0, hi = B;
    while (lo < hi) {
        int mid = (lo + hi) >> 1;
        if (__ldg(off + mid) <= i) lo = mid + 1; else hi = mid;
    }
    return lo;
}
__device__ __forceinline__ int gridKey(float c, float s, int G) {
    int g = (int)floorf((c - s) * INV_VOXEL);
    return min(max(g, 0), G - 1);
}
__device__ __forceinline__ void red4(float4* p, float x, float y, float z, float w) {
    asm volatile("red.global.add.v4.f32 [%0], {%1,%2,%3,%4};"
                 :: "l"(p), "f"(x), "f"(y), "f"(z), "f"(w) : "memory");
}

__global__ void kInit(int n) {
    int i = blockIdx.x * blockDim.x + threadIdx.x;
    if (i < n) { d_minMapped[i] = 0xFFFFFFFFu; d_maxMapped[i] = 0u; }
}

// per-batch min AND max, 8 points/thread, float4 loads
__global__ void kMinMax(const float* __restrict__ coord, const int* __restrict__ off,
                        int N, int B) {
    const unsigned full = 0xFFFFFFFFu;
    int t = blockIdx.x * blockDim.x + threadIdx.x;
    long long base = (long long)t * 8;
    if (base >= N) return;
    int i0 = (int)base;
    int cnt = min(8, N - i0);
    int bf = batchOf(i0, off, B);
    int bl = batchOf(i0 + cnt - 1, off, B);
    if (bf != bl) {   // rare: spans a batch boundary -> per-point atomics
        for (int i = i0; i < i0 + cnt; i++) {
            int b = batchOf(i, off, B);
            #pragma unroll
            for (int ax = 0; ax < 3; ax++) {
                float v = __ldg(coord + 3 * i + ax);
                atomicMin(&d_minMapped[3 * b + ax], fmap(v));
                atomicMax(&d_maxMapped[3 * b + ax], fmap(v));
            }
        }
        return;
    }
    float mn[3] = { 3.4e38f, 3.4e38f, 3.4e38f };
    float mx[3] = { -3.4e38f, -3.4e38f, -3.4e38f };
    if (cnt == 8) {
        const float4* p = reinterpret_cast<const float4*>(coord + (size_t)i0 * 3);
        #pragma unroll
        for (int k = 0; k < 6; k++) {
            float4 v = __ldg(p + k);
            float a[4] = { v.x, v.y, v.z, v.w };
            #pragma unroll
            for (int j = 0; j < 4; j++) {
                int ax = (4 * k + j) % 3;   // compile-time
                mn[ax] = fminf(mn[ax], a[j]);
                mx[ax] = fmaxf(mx[ax], a[j]);
            }
        }
    } else {
        for (int i = i0; i < i0 + cnt; i++) {
            #pragma unroll
            for (int ax = 0; ax < 3; ax++) {
                float v = __ldg(coord + 3 * i + ax);
                mn[ax] = fminf(mn[ax], v);
                mx[ax] = fmaxf(mx[ax], v);
            }
        }
    }
    unsigned act = __activemask();
    if (act == full) {
        int b0 = __shfl_sync(full, bf, 0);
        if (__all_sync(full, bf == b0)) {
            #pragma unroll
            for (int o = 16; o > 0; o >>= 1) {
                #pragma unroll
                for (int ax = 0; ax < 3; ax++) {
                    mn[ax] = fminf(mn[ax], __shfl_down_sync(full, mn[ax], o));
                    mx[ax] = fmaxf(mx[ax], __shfl_down_sync(full, mx[ax], o));
                }
            }
            if ((threadIdx.x & 31) == 0) {
                #pragma unroll
                for (int ax = 0; ax < 3; ax++) {
                    atomicMin(&d_minMapped[3 * bf + ax], fmap(mn[ax]));
                    atomicMax(&d_maxMapped[3 * bf + ax], fmap(mx[ax]));
                }
            }
            return;
        }
    }
    #pragma unroll
    for (int ax = 0; ax < 3; ax++) {
        atomicMin(&d_minMapped[3 * bf + ax], fmap(mn[ax]));
        atomicMax(&d_maxMapped[3 * bf + ax], fmap(mx[ax]));
    }
}

// start[], G, G3, word/chunk geometry, ticket reset
__global__ void kSetup(int B) {
    __shared__ int sm[256];
    int m = 0;
    for (int b = threadIdx.x; b < B; b += 256) {
        #pragma unroll
        for (int ax = 0; ax < 3; ax++) {
            float s = funmap(d_minMapped[3 * b + ax]);
            float M = funmap(d_maxMapped[3 * b + ax]);
            d_start[3 * b + ax] = s;
            int e = (int)floorf((M - s) * INV_VOXEL);  // == max per-point grid idx
            m = max(m, e);
        }
    }
    sm[threadIdx.x] = m; __syncthreads();
    for (int o = 128; o > 0; o >>= 1) {
        if (threadIdx.x < o) sm[threadIdx.x] = max(sm[threadIdx.x], sm[threadIdx.x + o]);
        __syncthreads();
    }
    if (threadIdx.x == 0) {
        int G = sm[0] + 1;
        long long ks = (long long)B * G * G * G;
        if (ks > MAXKEYS) ks = MAXKEYS;
        int W = (int)((ks >> 5) + 2);               // +2 covers boundary prefix
        int nc = (W + WCHUNK - 1) / WCHUNK;
        d_G = G; d_G3 = G * G * G;
        d_nWChunks = nc; d_nWordsPad = nc * WCHUNK;
        d_ticket = 0u;
    }
}

// zero bitmap pairs (~4MB) + tile status
__global__ void kZeroOcc() {
    int idx = blockIdx.x * blockDim.x + threadIdx.x;
    int stride = gridDim.x * blockDim.x;
    int n4 = d_nWordsPad >> 1;                      // uint4 = 2 pairs
    uint4 z = make_uint4(0u, 0u, 0u, 0u);
    uint4* p = reinterpret_cast<uint4*>(d_occ);
    for (int k = idx; k < n4; k += stride) p[k] = z;
    int nc = d_nWChunks;
    for (int k = idx; k < nc; k += stride) d_tileStatus[k] = 0u;
}

// fused grid + occupancy bitmap, 8 points/thread
__global__ void kGridHist(const float* __restrict__ coord, const int* __restrict__ off,
                          int N, int B) {
    int t = blockIdx.x * blockDim.x + threadIdx.x;
    long long base = (long long)t * 8;
    if (base >= N) return;
    int i0 = (int)base;
    int G = d_G;
    if (i0 + 7 < N) {
        const float4* c4 = reinterpret_cast<const float4*>(coord + (size_t)i0 * 3);
        float a[24];
        #pragma unroll
        for (int k = 0; k < 6; k++) {
            float4 v = __ldg(c4 + k);
            a[4 * k + 0] = v.x; a[4 * k + 1] = v.y;
            a[4 * k + 2] = v.z; a[4 * k + 3] = v.w;
        }
        int bf = batchOf(i0, off, B);
        int bl = batchOf(i0 + 7, off, B);
        int keys[8];
        #pragma unroll
        for (int k = 0; k < 8; k++) {
            int b = (bf == bl) ? bf : batchOf(i0 + k, off, B);
            float sx = d_start[3 * b + 0];
            float sy = d_start[3 * b + 1];
            float sz = d_start[3 * b + 2];
            int gx = gridKey(a[3 * k + 0], sx, G);
            int gy = gridKey(a[3 * k + 1], sy, G);
            int gz = gridKey(a[3 * k + 2], sz, G);
            keys[k] = ((b * G + gx) * G + gy) * G + gz;
        }
        #pragma unroll
        for (int k = 0; k < 8; k++)
            atomicOr(&d_occ[keys[k] >> 5].x, 1u << (keys[k] & 31));
    } else {
        for (int i = i0; i < N; i++) {
            int b = batchOf(i, off, B);
            int gx = gridKey(__ldg(coord + 3 * i + 0), d_start[3 * b + 0], G);
            int gy = gridKey(__ldg(coord + 3 * i + 1), d_start[3 * b + 1], G);
            int gz = gridKey(__ldg(coord + 3 * i + 2), d_start[3 * b + 2], G);
            int key = ((b * G + gx) * G + gy) * G + gz;
            atomicOr(&d_occ[key >> 5].x, 1u << (key & 31));
        }
    }
}

// popcount + decoupled-lookback prefix over bitmap words; fills pair.prefix,
// zeros this chunk's scratch rows, exports nVox
__global__ void __launch_bounds__(RT) kRankW() {
    __shared__ unsigned sChunk, sPrefix, sTotal;
    __shared__ unsigned warpS[RT / 32], wexcl[RT / 32];
    const unsigned full = 0xFFFFFFFFu;
    const int nChunks = d_nWChunks;
    while (true) {
        if (threadIdx.x == 0) sChunk = atomicAdd(&d_ticket, 1u);
        __syncthreads();
        unsigned chunk = sChunk;
        if (chunk >= (unsigned)nChunks) return;
        // 16 words per thread = 8 uint4 (2 pairs each)
        uint4* p = reinterpret_cast<uint4*>(d_occ) + chunk * (WCHUNK / 2)
                   + threadIdx.x * (WORDS_PT / 2);
        uint4 v[WORDS_PT / 2];
        unsigned tot = 0;
        #pragma unroll
        for (int k = 0; k < WORDS_PT / 2; k++) {
            v[k] = p[k];
            tot += __popc(v[k].x) + __popc(v[k].z);
        }
        int lane = threadIdx.x & 31, wid = threadIdx.x >> 5;
        unsigned incl = tot;
        #pragma unroll
        for (int o = 1; o < 32; o <<= 1) {
            unsigned a = __shfl_up_sync(full, incl, o);
            if (lane >= o) incl += a;
        }
        if (lane == 31) warpS[wid] = incl;
        __syncthreads();
        if (threadIdx.x == 0) {
            unsigned run = 0;
            #pragma unroll
            for (int w = 0; w < RT / 32; w++) { unsigned x = warpS[w]; wexcl[w] = run; run += x; }
            sTotal = run;
            if (chunk == 0) { atomicExch(&d_tileStatus[0], ST_INC | run); sPrefix = 0u; }
            else            atomicExch(&d_tileStatus[chunk], ST_AGG | run);
        }
        __syncthreads();
        if (chunk != 0 && wid == 0) {
            unsigned prefix = 0; int wbase = (int)chunk;
            while (true) {
                int j = wbase - 1 - lane;
                unsigned st = (j >= 0) ? *((volatile unsigned*)&d_tileStatus[j]) : ST_INC;
                if (!__all_sync(full, st != 0u)) continue;
                unsigned incmask = __ballot_sync(full, (st & ST_INC) != 0u);
                unsigned x;
                if (incmask) {
                    int closest = __ffs(incmask) - 1;
                    x = (lane <= closest) ? (st & VALMASK) : 0u;
                } else {
                    x = st & VALMASK;
                }
                #pragma unroll
                for (int o = 16; o > 0; o >>= 1) x += __shfl_down_sync(full, x, o);
                prefix += __shfl_sync(full, x, 0);
                if (incmask) break;
                wbase -= 32;
            }
            if (lane == 0) {
                sPrefix = prefix;
                atomicExch(&d_tileStatus[chunk], ST_INC | (prefix + sTotal));
            }
        }
        __syncthreads();
        unsigned cpfx = sPrefix, ctot = sTotal;
        if (chunk == (unsigned)(nChunks - 1) && threadIdx.x == 0)
            d_nVox = (int)(cpfx + ctot);
        unsigned run = cpfx + wexcl[wid] + (incl - tot);
        #pragma unroll
        for (int k = 0; k < WORDS_PT / 2; k++) {
            v[k].y = run; run += __popc(v[k].x);
            v[k].w = run; run += __popc(v[k].z);
            p[k] = v[k];                                // write prefixes back
        }
        // zero this chunk's scratch rows for the scatter pass
        float4 z4 = make_float4(0.f, 0.f, 0.f, 0.f);
        for (unsigned i = threadIdx.x; i < ctot; i += RT)
            d_scratch[cpfx + i] = z4;
        __syncthreads();                                // smem reuse
    }
}

// n_o[b] = number of occupied keys < (b+1)*G^3
__global__ void kTail(float* __restrict__ out, int N, int B) {
    int b = blockIdx.x * blockDim.x + threadIdx.x;
    if (b >= B) return;
    int key = (b + 1) * d_G3;
    uint2 pr = d_occ[key >> 5];
    unsigned bit = (unsigned)(key & 31);
    unsigned mask = (1u << bit) - 1u;                   // ==0 when bit==0
    out[3 * N + b] = (float)(pr.y + __popc(pr.x & mask));
}

// scatter: recompute key, rank from bitmap+prefix (one 8B gather), one red.v4
__global__ void kScatter(const float* __restrict__ coord, const int* __restrict__ off,
                         int N, int B) {
    int t = blockIdx.x * blockDim.x + threadIdx.x;
    long long base = (long long)t * 8;
    if (base >= N) return;
    int i0 = (int)base;
    int G = d_G;
    if (i0 + 7 < N) {
        const float4* c4 = reinterpret_cast<const float4*>(coord + (size_t)i0 * 3);
        float a[24];
        #pragma unroll
        for (int k = 0; k < 6; k++) {
            float4 v = __ldg(c4 + k);
            a[4 * k + 0] = v.x; a[4 * k + 1] = v.y;
            a[4 * k + 2] = v.z; a[4 * k + 3] = v.w;
        }
        int bf = batchOf(i0, off, B);
        int bl = batchOf(i0 + 7, off, B);
        unsigned r[8];
        #pragma unroll
        for (int k = 0; k < 8; k++) {
            int b = (bf == bl) ? bf : batchOf(i0 + k, off, B);
            float sx = d_start[3 * b + 0];
            float sy = d_start[3 * b + 1];
            float sz = d_start[3 * b + 2];
            int gx = gridKey(a[3 * k + 0], sx, G);
            int gy = gridKey(a[3 * k + 1], sy, G);
            int gz = gridKey(a[3 * k + 2], sz, G);
            int key = ((b * G + gx) * G + gy) * G + gz;
            uint2 pr = __ldg(&d_occ[key >> 5]);
            unsigned bit = (unsigned)(key & 31);
            r[k] = pr.y + __popc(pr.x & ((1u << bit) - 1u));
        }
        #pragma unroll
        for (int k = 0; k < 8; k++)
            red4(&d_scratch[r[k]], a[3 * k + 0], a[3 * k + 1], a[3 * k + 2], 1.0f);
    } else {
        for (int i = i0; i < N; i++) {
            int b = batchOf(i, off, B);
            float x = __ldg(coord + 3 * i + 0);
            float y = __ldg(coord + 3 * i + 1);
            float z = __ldg(coord + 3 * i + 2);
            int gx = gridKey(x, d_start[3 * b + 0], G);
            int gy = gridKey(y, d_start[3 * b + 1], G);
            int gz = gridKey(z, d_start[3 * b + 2], G);
            int key = ((b * G + gx) * G + gy) * G + gz;
            uint2 pr = __ldg(&d_occ[key >> 5]);
            unsigned bit = (unsigned)(key & 31);
            unsigned r = pr.y + __popc(pr.x & ((1u << bit) - 1u));
            red4(&d_scratch[r], x, y, z, 1.0f);
        }
    }
}

// writes ALL of n_p and counts: means for live rows, zeros for the tail
__global__ void kFinalize(float* __restrict__ out, int N, int B) {
    int nVox = d_nVox;
    int q = blockIdx.x * blockDim.x + threadIdx.x;
    int r0 = q * 4;
    if (r0 >= N) return;
    float* out_counts = out + 3 * N + B;
    if (r0 + 3 < nVox) {                                // all live: vector path
        float4 s0 = __ldg(d_scratch + r0 + 0);
        float4 s1 = __ldg(d_scratch + r0 + 1);
        float4 s2 = __ldg(d_scratch + r0 + 2);
        float4 s3 = __ldg(d_scratch + r0 + 3);
        float4 v0, v1, v2;
        v0.x = __fdiv_rn(s0.x, s0.w); v0.y = __fdiv_rn(s0.y, s0.w); v0.z = __fdiv_rn(s0.z, s0.w);
        v0.w = __fdiv_rn(s1.x, s1.w); v1.x = __fdiv_rn(s1.y, s1.w); v1.y = __fdiv_rn(s1.z, s1.w);
        v1.z = __fdiv_rn(s2.x, s2.w); v1.w = __fdiv_rn(s2.y, s2.w); v2.x = __fdiv_rn(s2.z, s2.w);
        v2.y = __fdiv_rn(s3.x, s3.w); v2.z = __fdiv_rn(s3.y, s3.w); v2.w = __fdiv_rn(s3.z, s3.w);
        float4* p = reinterpret_cast<float4*>(out) + (size_t)q * 3;
        p[0] = v0; p[1] = v1; p[2] = v2;
        out_counts[r0 + 0] = s0.w; out_counts[r0 + 1] = s1.w;
        out_counts[r0 + 2] = s2.w; out_counts[r0 + 3] = s3.w;
    } else if (r0 >= nVox) {                            // all dead: zero path
        float4 z = make_float4(0.f, 0.f, 0.f, 0.f);
        float4* p = reinterpret_cast<float4*>(out) + (size_t)q * 3;
        if (r0 + 3 < N) {
            p[0] = z; p[1] = z; p[2] = z;
            out_counts[r0 + 0] = 0.f; out_counts[r0 + 1] = 0.f;
            out_counts[r0 + 2] = 0.f; out_counts[r0 + 3] = 0.f;
        } else {
            for (int r = r0; r < N; r++) {
                out[3 * r + 0] = 0.f; out[3 * r + 1] = 0.f; out[3 * r + 2] = 0.f;
                out_counts[r] = 0.f;
            }
        }
    } else {                                            // mixed quad
        for (int r = r0; r < min(r0 + 4, N); r++) {
            if (r < nVox) {
                float4 s = __ldg(d_scratch + r);
                out[3 * r + 0] = __fdiv_rn(s.x, s.w);
                out[3 * r + 1] = __fdiv_rn(s.y, s.w);
                out[3 * r + 2] = __fdiv_rn(s.z, s.w);
                out_counts[r] = s.w;
            } else {
                out[3 * r + 0] = 0.f; out[3 * r + 1] = 0.f; out[3 * r + 2] = 0.f;
                out_counts[r] = 0.f;
            }
        }
    }
}

extern "C" void kernel_launch(void* const* d_in, const int* in_sizes, int n_in,
                              void* d_out, int out_size) {
    const float* coord  = (const float*)d_in[0];
    const int*   offset = (const int*)d_in[1];
    int N = in_sizes[0] / 3;
    int B = in_sizes[1];
    float* out = (float*)d_out;

    int nb8 = (int)((N + 8LL * 256 - 1) / (8 * 256));
    int nbq = (int)((N + 4LL * 256 - 1) / (4 * 256));

    kInit<<<(3 * B + 255) / 256, 256>>>(3 * B);
    kMinMax<<<nb8, 256>>>(coord, offset, N, B);
    kSetup<<<1, 256>>>(B);
    kZeroOcc<<<512, 256>>>();
    kGridHist<<<nb8, 256>>>(coord, offset, N, B);
    kRankW<<<148, RT>>>();
    kTail<<<(B + 255) / 256, 256>>>(out, N, B);
    kScatter<<<nb8, 256>>>(coord, offset, N, B);
    kFinalize<<<nbq, 256>>>(out, N, B);
}